// round 11
// baseline (speedup 1.0000x reference)
#include <cuda_runtime.h>
#include <cstdint>
#include <cstddef>

#define TT 16            // tokens per tile
#define NC 1024          // flattened stream dim (n*C)
#define NTHR 512
#define FULLMASK 0xFFFFFFFFu

typedef unsigned long long ull;

// ---- packed f32x2 helpers (Blackwell FFMA2 path) ----
__device__ __forceinline__ void fma2(ull &acc, ull a, ull b) {
    asm("fma.rn.f32x2 %0, %1, %2, %0;" : "+l"(acc) : "l"(a), "l"(b));
}
__device__ __forceinline__ ull pack2(float x, float y) {
    ull r;
    asm("mov.b64 %0, {%1, %2};" : "=l"(r)
        : "r"(__float_as_uint(x)), "r"(__float_as_uint(y)));
    return r;
}
__device__ __forceinline__ float hadd2(ull v) {
    unsigned lo, hi;
    asm("mov.b64 {%0, %1}, %2;" : "=r"(lo), "=r"(hi) : "l"(v));
    return __uint_as_float(lo) + __uint_as_float(hi);
}

__device__ __forceinline__ void cp_async16(uint32_t saddr, const void* gaddr) {
    asm volatile("cp.async.cg.shared.global [%0], [%1], 16;"
                 :: "r"(saddr), "l"(gaddr));
}

// smem layout (floats):
//   xbuf0[TT*NC] | xbuf1[TT*NC] | rstd[TT] | dotsp[4][TT][24] | coef[TT*16] | bsm[24]
#define SMEM_FLOATS (2*TT*NC + TT + 4*TT*24 + TT*16 + 32)

__global__ __launch_bounds__(NTHR, 1)
void fused_streams_kernel(const float* __restrict__ x,
                          const float* __restrict__ scale,
                          const float* __restrict__ w_pre,
                          const float* __restrict__ w_post,
                          const float* __restrict__ w_res,
                          const float* __restrict__ p_apre,
                          const float* __restrict__ p_apost,
                          const float* __restrict__ p_ares,
                          const float* __restrict__ b_pre,
                          const float* __restrict__ b_post,
                          const float* __restrict__ b_res,
                          float* __restrict__ out,
                          int nTiles)
{
    extern __shared__ float smem[];
    float* xbuf0 = smem;
    float* xbuf1 = smem + TT*NC;
    float* rstd  = smem + 2*TT*NC;
    float* dotsp = rstd + TT;              // [4][TT][24]
    float* coef  = dotsp + 4*TT*24;        // [TT][16]
    float* bsm   = coef + TT*16;           // [24] biases

    const int tid  = threadIdx.x;
    const int lane = tid & 31;
    const int warp = tid >> 5;             // 0..15
    const int g    = warp >> 2;            // row group 0..3 (6 rows each)
    const int kq   = warp & 3;             // K-quarter 0..3

    const float a_pre  = *p_apre;
    const float a_post = *p_apost;
    const float a_res  = *p_ares;

    // biases into smem (read by Phase C)
    if (tid < 4)        bsm[tid]      = b_pre[tid];
    else if (tid < 8)   bsm[tid]      = b_post[tid - 4];
    else if (tid < 24)  bsm[tid]      = b_res[tid - 8];

    // ---- weight slice into registers (scale folded), 4-way K split ----
    // warp (g,kq): rows 6g..6g+5, K-quarter kq (256 floats). Lane owns float4
    // chunks idx = kq*64 + lane + 32m, m=0..1 -> 4 ull per row, 6 rows = 24 ull.
    ull wr[6][4];
#pragma unroll
    for (int q = 0; q < 6; q++) {
        int r = g*6 + q;
        const float* wrow = (r < 4)  ? (w_pre  + r*NC)
                          : (r < 8)  ? (w_post + (r-4)*NC)
                                     : (w_res  + (r-8)*NC);
        const float4* wrow4 = reinterpret_cast<const float4*>(wrow);
        const float4* sc4   = reinterpret_cast<const float4*>(scale);
#pragma unroll
        for (int m = 0; m < 2; m++) {
            int idx = kq*64 + lane + 32*m;
            float4 wv = wrow4[idx];
            float4 sv = sc4[idx];
            wr[q][2*m]   = pack2(wv.x * sv.x, wv.y * sv.y);
            wr[q][2*m+1] = pack2(wv.z * sv.z, wv.w * sv.w);
        }
    }

    uint32_t sb0 = (uint32_t)__cvta_generic_to_shared(xbuf0);
    uint32_t sb1 = (uint32_t)__cvta_generic_to_shared(xbuf1);

    int tile = blockIdx.x;

    // prefetch first tile into buffer 0 (64KB, 512 threads x 16B x 8)
    if (tile < nTiles) {
        const char* src = (const char*)(x + (size_t)tile * (TT*NC));
#pragma unroll
        for (int j = 0; j < 8; j++) {
            int off = j*8192 + tid*16;
            cp_async16(sb0 + off, src + off);
        }
    }
    asm volatile("cp.async.commit_group;");

    int buf = 0;
    for (; tile < nTiles; tile += gridDim.x) {
        // prefetch next tile into the other buffer
        int nxt = tile + gridDim.x;
        if (nxt < nTiles) {
            uint32_t sbn = buf ? sb0 : sb1;
            const char* src = (const char*)(x + (size_t)nxt * (TT*NC));
#pragma unroll
            for (int j = 0; j < 8; j++) {
                int off = j*8192 + tid*16;
                cp_async16(sbn + off, src + off);
            }
        }
        asm volatile("cp.async.commit_group;");
        asm volatile("cp.async.wait_group 1;");   // current tile resident
        __syncthreads();

        const float* xb = buf ? xbuf1 : xbuf0;

        // ---- Phase A: per-token RMS rstd (warp per token) ----
        {
            int t = warp;
            const float4* x4 = reinterpret_cast<const float4*>(xb) + t*256;
            float s = 0.f;
#pragma unroll
            for (int i = 0; i < 8; i++) {
                float4 v = x4[lane + 32*i];
                s += v.x*v.x + v.y*v.y + v.z*v.z + v.w*v.w;
            }
            s += __shfl_xor_sync(FULLMASK, s, 16);
            s += __shfl_xor_sync(FULLMASK, s, 8);
            s += __shfl_xor_sync(FULLMASK, s, 4);
            s += __shfl_xor_sync(FULLMASK, s, 2);
            s += __shfl_xor_sync(FULLMASK, s, 1);
            if (lane == 0) rstd[t] = rsqrtf(s * (1.0f/1024.0f) + 1e-5f);
        }

        // ---- Phase B: partial dots, warp = 6 rows x K/4, 2-token batches ----
        for (int t = 0; t < TT; t += 2) {
            const float4* xA = reinterpret_cast<const float4*>(xb + t*NC)     + kq*64;
            const float4* xB = reinterpret_cast<const float4*>(xb + (t+1)*NC) + kq*64;
            float4 va0 = xA[lane], va1 = xA[lane + 32];
            float4 vb0 = xB[lane], vb1 = xB[lane + 32];
            ull a0 = pack2(va0.x, va0.y), a1 = pack2(va0.z, va0.w);
            ull a2 = pack2(va1.x, va1.y), a3 = pack2(va1.z, va1.w);
            ull b0 = pack2(vb0.x, vb0.y), b1 = pack2(vb0.z, vb0.w);
            ull b2 = pack2(vb1.x, vb1.y), b3 = pack2(vb1.z, vb1.w);
            ull accA[6], accB[6];
#pragma unroll
            for (int q = 0; q < 6; q++) { accA[q] = 0ull; accB[q] = 0ull; }
#pragma unroll
            for (int q = 0; q < 6; q++) {
                fma2(accA[q], wr[q][0], a0);
                fma2(accA[q], wr[q][1], a1);
                fma2(accA[q], wr[q][2], a2);
                fma2(accA[q], wr[q][3], a3);
                fma2(accB[q], wr[q][0], b0);
                fma2(accB[q], wr[q][1], b1);
                fma2(accB[q], wr[q][2], b2);
                fma2(accB[q], wr[q][3], b3);
            }
            float dA[6], dB[6];
#pragma unroll
            for (int q = 0; q < 6; q++) { dA[q] = hadd2(accA[q]); dB[q] = hadd2(accB[q]); }
            // coset reduce: xor16 + xor8 -> lane l holds coset (l&7) sum
#pragma unroll
            for (int q = 0; q < 6; q++) {
                dA[q] += __shfl_xor_sync(FULLMASK, dA[q], 16);
                dB[q] += __shfl_xor_sync(FULLMASK, dB[q], 16);
            }
#pragma unroll
            for (int q = 0; q < 6; q++) {
                dA[q] += __shfl_xor_sync(FULLMASK, dA[q], 8);
                dB[q] += __shfl_xor_sync(FULLMASK, dB[q], 8);
            }
            // octet o reduces value o (e1) and value 4+o for o<2 (e2)
            int oct = lane >> 3;
            float e1A = (oct == 0) ? dA[0] : (oct == 1) ? dA[1] : (oct == 2) ? dA[2] : dA[3];
            float e2A = (oct == 0) ? dA[4] : dA[5];
            float e1B = (oct == 0) ? dB[0] : (oct == 1) ? dB[1] : (oct == 2) ? dB[2] : dB[3];
            float e2B = (oct == 0) ? dB[4] : dB[5];
#pragma unroll
            for (int m = 4; m >= 1; m >>= 1) {
                e1A += __shfl_xor_sync(FULLMASK, e1A, m);
                e2A += __shfl_xor_sync(FULLMASK, e2A, m);
                e1B += __shfl_xor_sync(FULLMASK, e1B, m);
                e2B += __shfl_xor_sync(FULLMASK, e2B, m);
            }
            if ((lane & 7) == 0) {
                float* dpt = dotsp + kq*(TT*24) + g*6;
                dpt[t*24 + oct] = e1A;
                dpt[(t+1)*24 + oct] = e1B;
                if (oct < 2) {
                    dpt[t*24 + 4 + oct] = e2A;
                    dpt[(t+1)*24 + 4 + oct] = e2B;
                }
            }
        }
        __syncthreads();

        // ---- Phase C: thread-per-token sinkhorn + routing (threads 0..15) ----
        if (tid < TT) {
            int t = tid;
            float rs = rstd[t];
            float ar = a_res * rs;

            // gather res-logit rows (w_res rows 0..15 -> matrix [i][j], i=row)
            float4 z0, z1, z2, z3;
            {
                const float4* p0 = reinterpret_cast<const float4*>(dotsp + 0*(TT*24) + t*24);
                const float4* p1 = reinterpret_cast<const float4*>(dotsp + 1*(TT*24) + t*24);
                const float4* p2 = reinterpret_cast<const float4*>(dotsp + 2*(TT*24) + t*24);
                const float4* p3 = reinterpret_cast<const float4*>(dotsp + 3*(TT*24) + t*24);
                float4 s2, s3, s4, s5, q;
                s2 = p0[2]; q = p1[2]; s2.x+=q.x; s2.y+=q.y; s2.z+=q.z; s2.w+=q.w;
                q = p2[2]; s2.x+=q.x; s2.y+=q.y; s2.z+=q.z; s2.w+=q.w;
                q = p3[2]; s2.x+=q.x; s2.y+=q.y; s2.z+=q.z; s2.w+=q.w;
                s3 = p0[3]; q = p1[3]; s3.x+=q.x; s3.y+=q.y; s3.z+=q.z; s3.w+=q.w;
                q = p2[3]; s3.x+=q.x; s3.y+=q.y; s3.z+=q.z; s3.w+=q.w;
                q = p3[3]; s3.x+=q.x; s3.y+=q.y; s3.z+=q.z; s3.w+=q.w;
                s4 = p0[4]; q = p1[4]; s4.x+=q.x; s4.y+=q.y; s4.z+=q.z; s4.w+=q.w;
                q = p2[4]; s4.x+=q.x; s4.y+=q.y; s4.z+=q.z; s4.w+=q.w;
                q = p3[4]; s4.x+=q.x; s4.y+=q.y; s4.z+=q.z; s4.w+=q.w;
                s5 = p0[5]; q = p1[5]; s5.x+=q.x; s5.y+=q.y; s5.z+=q.z; s5.w+=q.w;
                q = p2[5]; s5.x+=q.x; s5.y+=q.y; s5.z+=q.z; s5.w+=q.w;
                q = p3[5]; s5.x+=q.x; s5.y+=q.y; s5.z+=q.z; s5.w+=q.w;
                z0 = make_float4(fmaf(ar, s2.x, bsm[8]),  fmaf(ar, s2.y, bsm[9]),
                                 fmaf(ar, s2.z, bsm[10]), fmaf(ar, s2.w, bsm[11]));
                z1 = make_float4(fmaf(ar, s3.x, bsm[12]), fmaf(ar, s3.y, bsm[13]),
                                 fmaf(ar, s3.z, bsm[14]), fmaf(ar, s3.w, bsm[15]));
                z2 = make_float4(fmaf(ar, s4.x, bsm[16]), fmaf(ar, s4.y, bsm[17]),
                                 fmaf(ar, s4.z, bsm[18]), fmaf(ar, s4.w, bsm[19]));
                z3 = make_float4(fmaf(ar, s5.x, bsm[20]), fmaf(ar, s5.y, bsm[21]),
                                 fmaf(ar, s5.z, bsm[22]), fmaf(ar, s5.w, bsm[23]));
            }
            // max over 16
            float mx = fmaxf(fmaxf(fmaxf(z0.x, z0.y), fmaxf(z0.z, z0.w)),
                      fmaxf(fmaxf(fmaxf(z1.x, z1.y), fmaxf(z1.z, z1.w)),
                      fmaxf(fmaxf(fmaxf(z2.x, z2.y), fmaxf(z2.z, z2.w)),
                            fmaxf(fmaxf(z3.x, z3.y), fmaxf(z3.z, z3.w)))));
            float4 q0, q1, q2, q3;   // the doubly-stochastic iterate
            q0 = make_float4(__expf(z0.x-mx), __expf(z0.y-mx), __expf(z0.z-mx), __expf(z0.w-mx));
            q1 = make_float4(__expf(z1.x-mx), __expf(z1.y-mx), __expf(z1.z-mx), __expf(z1.w-mx));
            q2 = make_float4(__expf(z2.x-mx), __expf(z2.y-mx), __expf(z2.z-mx), __expf(z2.w-mx));
            q3 = make_float4(__expf(z3.x-mx), __expf(z3.y-mx), __expf(z3.z-mx), __expf(z3.w-mx));

#pragma unroll
            for (int it = 0; it < 20; it++) {
                // column normalize (sum over rows i)
                float4 ic;
                ic.x = __fdividef(1.f, (q0.x + q1.x) + (q2.x + q3.x) + 1e-8f);
                ic.y = __fdividef(1.f, (q0.y + q1.y) + (q2.y + q3.y) + 1e-8f);
                ic.z = __fdividef(1.f, (q0.z + q1.z) + (q2.z + q3.z) + 1e-8f);
                ic.w = __fdividef(1.f, (q0.w + q1.w) + (q2.w + q3.w) + 1e-8f);
                q0.x *= ic.x; q0.y *= ic.y; q0.z *= ic.z; q0.w *= ic.w;
                q1.x *= ic.x; q1.y *= ic.y; q1.z *= ic.z; q1.w *= ic.w;
                q2.x *= ic.x; q2.y *= ic.y; q2.z *= ic.z; q2.w *= ic.w;
                q3.x *= ic.x; q3.y *= ic.y; q3.z *= ic.z; q3.w *= ic.w;
                // row normalize (sum over cols j)
                float i0 = __fdividef(1.f, (q0.x + q0.y) + (q0.z + q0.w) + 1e-8f);
                float i1 = __fdividef(1.f, (q1.x + q1.y) + (q1.z + q1.w) + 1e-8f);
                float i2 = __fdividef(1.f, (q2.x + q2.y) + (q2.z + q2.w) + 1e-8f);
                float i3 = __fdividef(1.f, (q3.x + q3.y) + (q3.z + q3.w) + 1e-8f);
                q0.x *= i0; q0.y *= i0; q0.z *= i0; q0.w *= i0;
                q1.x *= i1; q1.y *= i1; q1.z *= i1; q1.w *= i1;
                q2.x *= i2; q2.y *= i2; q2.z *= i2; q2.w *= i2;
                q3.x *= i3; q3.y *= i3; q3.z *= i3; q3.w *= i3;
            }

            // pre/post gates (rows 0..7 of the stacked dots)
            float hpre[4], hpost[4];
            {
                const float* d0 = dotsp + 0*(TT*24) + t*24;
                const float* d1 = dotsp + 1*(TT*24) + t*24;
                const float* d2 = dotsp + 2*(TT*24) + t*24;
                const float* d3 = dotsp + 3*(TT*24) + t*24;
#pragma unroll
                for (int r = 0; r < 4; r++) {
                    float dd = (d0[r] + d1[r]) + (d2[r] + d3[r]);
                    hpre[r] = __fdividef(1.0f, 1.0f + __expf(-fmaf(a_pre, dd*rs, bsm[r])));
                }
#pragma unroll
                for (int r = 0; r < 4; r++) {
                    float dd = (d0[4+r] + d1[4+r]) + (d2[4+r] + d3[4+r]);
                    hpost[r] = __fdividef(2.0f, 1.0f + __expf(-fmaf(a_post, dd*rs, bsm[4+r])));
                }
            }
            // M[i][j] = q[i][j] + hpost[i]*hpre[j]
            float4* cf4 = reinterpret_cast<float4*>(coef + t*16);
            cf4[0] = make_float4(fmaf(hpost[0], hpre[0], q0.x), fmaf(hpost[0], hpre[1], q0.y),
                                 fmaf(hpost[0], hpre[2], q0.z), fmaf(hpost[0], hpre[3], q0.w));
            cf4[1] = make_float4(fmaf(hpost[1], hpre[0], q1.x), fmaf(hpost[1], hpre[1], q1.y),
                                 fmaf(hpost[1], hpre[2], q1.z), fmaf(hpost[1], hpre[3], q1.w));
            cf4[2] = make_float4(fmaf(hpost[2], hpre[0], q2.x), fmaf(hpost[2], hpre[1], q2.y),
                                 fmaf(hpost[2], hpre[2], q2.z), fmaf(hpost[2], hpre[3], q2.w));
            cf4[3] = make_float4(fmaf(hpost[3], hpre[0], q3.x), fmaf(hpost[3], hpre[1], q3.y),
                                 fmaf(hpost[3], hpre[2], q3.z), fmaf(hpost[3], hpre[3], q3.w));
        }
        __syncthreads();

        // ---- Phase D: mixing out[t][i][c] = sum_j M[i][j] * x[t][j][c] ----
        {
            int c4 = tid & 63;     // float4 column chunk (C=256 -> 64 chunks)
            int tg = tid >> 6;     // token group 0..7
            const float4* cf4 = reinterpret_cast<const float4*>(coef);
#pragma unroll
            for (int ttk = 0; ttk < 2; ttk++) {
                int t = tg*2 + ttk;
                float4 m0 = cf4[t*4 + 0];
                float4 m1 = cf4[t*4 + 1];
                float4 m2 = cf4[t*4 + 2];
                float4 m3 = cf4[t*4 + 3];
                const float4* x4 = reinterpret_cast<const float4*>(xb) + t*256;
                float4 xj0 = x4[0*64 + c4];
                float4 xj1 = x4[1*64 + c4];
                float4 xj2 = x4[2*64 + c4];
                float4 xj3 = x4[3*64 + c4];
                float4* o4 = reinterpret_cast<float4*>(out)
                           + ((size_t)tile*TT + t) * 256;
                float4 o;
                o.x = m0.x*xj0.x + m0.y*xj1.x + m0.z*xj2.x + m0.w*xj3.x;
                o.y = m0.x*xj0.y + m0.y*xj1.y + m0.z*xj2.y + m0.w*xj3.y;
                o.z = m0.x*xj0.z + m0.y*xj1.z + m0.z*xj2.z + m0.w*xj3.z;
                o.w = m0.x*xj0.w + m0.y*xj1.w + m0.z*xj2.w + m0.w*xj3.w;
                o4[0*64 + c4] = o;
                o.x = m1.x*xj0.x + m1.y*xj1.x + m1.z*xj2.x + m1.w*xj3.x;
                o.y = m1.x*xj0.y + m1.y*xj1.y + m1.z*xj2.y + m1.w*xj3.y;
                o.z = m1.x*xj0.z + m1.y*xj1.z + m1.z*xj2.z + m1.w*xj3.z;
                o.w = m1.x*xj0.w + m1.y*xj1.w + m1.z*xj2.w + m1.w*xj3.w;
                o4[1*64 + c4] = o;
                o.x = m2.x*xj0.x + m2.y*xj1.x + m2.z*xj2.x + m2.w*xj3.x;
                o.y = m2.x*xj0.y + m2.y*xj1.y + m2.z*xj2.y + m2.w*xj3.y;
                o.z = m2.x*xj0.z + m2.y*xj1.z + m2.z*xj2.z + m2.w*xj3.z;
                o.w = m2.x*xj0.w + m2.y*xj1.w + m2.z*xj2.w + m2.w*xj3.w;
                o4[2*64 + c4] = o;
                o.x = m3.x*xj0.x + m3.y*xj1.x + m3.z*xj2.x + m3.w*xj3.x;
                o.y = m3.x*xj0.y + m3.y*xj1.y + m3.z*xj2.y + m3.w*xj3.y;
                o.z = m3.x*xj0.z + m3.y*xj1.z + m3.z*xj2.z + m3.w*xj3.z;
                o.w = m3.x*xj0.w + m3.y*xj1.w + m3.z*xj2.w + m3.w*xj3.w;
                o4[3*64 + c4] = o;
            }
        }
        __syncthreads();   // xb free for reuse by the prefetch 2 tiles ahead
        buf ^= 1;
    }
}

extern "C" void kernel_launch(void* const* d_in, const int* in_sizes, int n_in,
                              void* d_out, int out_size) {
    const float* x      = (const float*)d_in[0];
    const float* scale  = (const float*)d_in[1];
    const float* w_pre  = (const float*)d_in[2];
    const float* w_post = (const float*)d_in[3];
    const float* w_res  = (const float*)d_in[4];
    const float* apre   = (const float*)d_in[5];
    const float* apost  = (const float*)d_in[6];
    const float* ares   = (const float*)d_in[7];
    const float* b_pre  = (const float*)d_in[8];
    const float* b_post = (const float*)d_in[9];
    const float* b_res  = (const float*)d_in[10];
    float* out = (float*)d_out;

    int BT = in_sizes[0] / NC;        // 32768 tokens
    int nTiles = BT / TT;             // 2048

    size_t smemBytes = (size_t)SMEM_FLOATS * sizeof(float);   // ~139 KB

    int dev = 0;
    cudaGetDevice(&dev);
    int sms = 148;
    cudaDeviceGetAttribute(&sms, cudaDevAttrMultiProcessorCount, dev);
    cudaFuncSetAttribute(fused_streams_kernel,
                         cudaFuncAttributeMaxDynamicSharedMemorySize,
                         (int)smemBytes);

    int grid = sms < nTiles ? sms : nTiles;

    fused_streams_kernel<<<grid, NTHR, smemBytes>>>(
        x, scale, w_pre, w_post, w_res,
        apre, apost, ares, b_pre, b_post, b_res,
        out, nTiles);
}

// round 12
// speedup vs baseline: 1.3504x; 1.3504x over previous
#include <cuda_runtime.h>
#include <cstdint>
#include <cstddef>

#define TT 16            // tokens per tile
#define NC 1024          // flattened stream dim (n*C)
#define NTHR 384
#define FULLMASK 0xFFFFFFFFu

typedef unsigned long long ull;

// ---- packed f32x2 helpers (Blackwell FFMA2 path) ----
__device__ __forceinline__ void fma2(ull &acc, ull a, ull b) {
    asm("fma.rn.f32x2 %0, %1, %2, %0;" : "+l"(acc) : "l"(a), "l"(b));
}
__device__ __forceinline__ ull pack2(float x, float y) {
    ull r;
    asm("mov.b64 %0, {%1, %2};" : "=l"(r)
        : "r"(__float_as_uint(x)), "r"(__float_as_uint(y)));
    return r;
}
__device__ __forceinline__ float hadd2(ull v) {
    unsigned lo, hi;
    asm("mov.b64 {%0, %1}, %2;" : "=r"(lo), "=r"(hi) : "l"(v));
    return __uint_as_float(lo) + __uint_as_float(hi);
}

__device__ __forceinline__ void cp_async16(uint32_t saddr, const void* gaddr) {
    asm volatile("cp.async.cg.shared.global [%0], [%1], 16;"
                 :: "r"(saddr), "l"(gaddr));
}

// smem layout (floats):
//   xbuf0[TT*NC] | xbuf1[TT*NC] | dotsp[2][TT][24] | sqsm[2][TT] | coef[TT*16]
#define SMEM_FLOATS (2*TT*NC + 2*TT*24 + 2*TT + TT*16)

__global__ __launch_bounds__(NTHR, 1)
void fused_streams_kernel(const float* __restrict__ x,
                          const float* __restrict__ scale,
                          const float* __restrict__ w_pre,
                          const float* __restrict__ w_post,
                          const float* __restrict__ w_res,
                          const float* __restrict__ p_apre,
                          const float* __restrict__ p_apost,
                          const float* __restrict__ p_ares,
                          const float* __restrict__ b_pre,
                          const float* __restrict__ b_post,
                          const float* __restrict__ b_res,
                          float* __restrict__ out,
                          int nTiles)
{
    extern __shared__ float smem[];
    float* xbuf0 = smem;
    float* xbuf1 = smem + TT*NC;
    float* dotsp = smem + 2*TT*NC;        // [2][TT][24]
    float* sqsm  = dotsp + 2*TT*24;       // [2][TT]
    float* coef  = sqsm + 2*TT;           // [TT][16]

    const int tid  = threadIdx.x;
    const int lane = tid & 31;
    const int warp = tid >> 5;            // 0..11
    const int g    = warp >> 1;           // row group 0..5 (4 rows each)
    const int kh   = warp & 1;            // K-half 0/1
    const bool b16 = (lane & 16) != 0;
    const bool b8  = (lane & 8)  != 0;
    const bool b4  = (lane & 4)  != 0;

    const float a_pre  = *p_apre;
    const float a_post = *p_apost;
    const float a_res  = *p_ares;

    // Phase C per-thread constants (cell fixed): used by threads < 256
    const int c_cell = tid & 15;
    const float c_bres = b_res[c_cell];
    const float c_bph  = (c_cell < 4) ? b_pre[c_cell]
                       : (c_cell < 8) ? b_post[c_cell - 4] : 0.f;

    // ---- weight slice into registers (scale folded) ----
    // warp (g,kh): rows 4g..4g+3, K-half kh. Lane l owns float4 chunks
    // idx = kh*128 + l + 32m, m=0..3 -> 8 ull per row, 4 rows = 32 ull (64 regs)
    ull wr[4][8];
#pragma unroll
    for (int q = 0; q < 4; q++) {
        int r = g*4 + q;
        const float* wrow = (r < 4)  ? (w_pre  + r*NC)
                          : (r < 8)  ? (w_post + (r-4)*NC)
                                     : (w_res  + (r-8)*NC);
        const float4* wrow4 = reinterpret_cast<const float4*>(wrow);
        const float4* sc4   = reinterpret_cast<const float4*>(scale);
#pragma unroll
        for (int m = 0; m < 4; m++) {
            int idx = kh*128 + lane + 32*m;
            float4 wv = wrow4[idx];
            float4 sv = sc4[idx];
            wr[q][2*m]   = pack2(wv.x * sv.x, wv.y * sv.y);
            wr[q][2*m+1] = pack2(wv.z * sv.z, wv.w * sv.w);
        }
    }

    uint32_t sb0 = (uint32_t)__cvta_generic_to_shared(xbuf0);
    uint32_t sb1 = (uint32_t)__cvta_generic_to_shared(xbuf1);

    int tile = blockIdx.x;

    // prefetch first tile into buffer 0 (64KB over 384 threads)
    if (tile < nTiles) {
        const char* src = (const char*)(x + (size_t)tile * (TT*NC));
#pragma unroll
        for (int j = 0; j < 11; j++) {
            int off = j*6144 + tid*16;
            if (off < TT*NC*4) cp_async16(sb0 + off, src + off);
        }
    }
    asm volatile("cp.async.commit_group;");

    int buf = 0;
    for (; tile < nTiles; tile += gridDim.x) {
        // prefetch next tile into the other buffer
        int nxt = tile + gridDim.x;
        if (nxt < nTiles) {
            uint32_t sbn = buf ? sb0 : sb1;
            const char* src = (const char*)(x + (size_t)nxt * (TT*NC));
#pragma unroll
            for (int j = 0; j < 11; j++) {
                int off = j*6144 + tid*16;
                if (off < TT*NC*4) cp_async16(sbn + off, src + off);
            }
        }
        asm volatile("cp.async.commit_group;");
        asm volatile("cp.async.wait_group 1;");   // current tile resident
        __syncthreads();

        const float* xb = buf ? xbuf1 : xbuf0;

        // ---- Phase B: dots (+ folded x^2 sums), warp = 4 rows x K/2 ----
#pragma unroll
        for (int t = 0; t < TT; t += 2) {
            // warps g==0 own sq of tokens 0..7, g==1 own 8..15
            const bool doSq = (g == 0 && t < 8) || (g == 1 && t >= 8);

            const float4* xA = reinterpret_cast<const float4*>(xb + t*NC)     + kh*128;
            const float4* xB = reinterpret_cast<const float4*>(xb + (t+1)*NC) + kh*128;
            ull av[8], bv[8];
#pragma unroll
            for (int m = 0; m < 4; m++) {
                float4 va = xA[lane + 32*m];
                float4 vb = xB[lane + 32*m];
                av[2*m]   = pack2(va.x, va.y);
                av[2*m+1] = pack2(va.z, va.w);
                bv[2*m]   = pack2(vb.x, vb.y);
                bv[2*m+1] = pack2(vb.z, vb.w);
            }
            ull acc[8];
#pragma unroll
            for (int q = 0; q < 8; q++) acc[q] = 0ull;
#pragma unroll
            for (int m = 0; m < 8; m++) {
#pragma unroll
                for (int q = 0; q < 4; q++) {
                    fma2(acc[q],   wr[q][m], av[m]);
                    fma2(acc[4+q], wr[q][m], bv[m]);
                }
            }
            ull sqa = 0ull, sqb = 0ull;
            if (doSq) {
#pragma unroll
                for (int m = 0; m < 8; m++) {
                    fma2(sqa, av[m], av[m]);
                    fma2(sqb, bv[m], bv[m]);
                }
            }

            float v[8];
#pragma unroll
            for (int q = 0; q < 8; q++) v[q] = hadd2(acc[q]);
            // pack-butterfly reduce: 8 values over 32 lanes in 16 SHFL
            // v[0..3] = token t rows 0..3 ; v[4..7] = token t+1 rows 0..3
#pragma unroll
            for (int q = 0; q < 8; q++) v[q] += __shfl_xor_sync(FULLMASK, v[q], 16);
            float u0 = b16 ? v[4] : v[0];
            float u1 = b16 ? v[5] : v[1];
            float u2 = b16 ? v[6] : v[2];
            float u3 = b16 ? v[7] : v[3];
            u0 += __shfl_xor_sync(FULLMASK, u0, 8);
            u1 += __shfl_xor_sync(FULLMASK, u1, 8);
            u2 += __shfl_xor_sync(FULLMASK, u2, 8);
            u3 += __shfl_xor_sync(FULLMASK, u3, 8);
            float w0 = b8 ? u2 : u0;
            float w1 = b8 ? u3 : u1;
            w0 += __shfl_xor_sync(FULLMASK, w0, 4);
            w1 += __shfl_xor_sync(FULLMASK, w1, 4);
            float y = b4 ? w1 : w0;
            y += __shfl_xor_sync(FULLMASK, y, 2);
            y += __shfl_xor_sync(FULLMASK, y, 1);
            if ((lane & 3) == 0) {
                int tok = t + (b16 ? 1 : 0);
                int row = (b8 ? 2 : 0) + (b4 ? 1 : 0);
                dotsp[(kh*TT + tok)*24 + g*4 + row] = y;
            }
            if (doSq) {
                float s0 = hadd2(sqa), s1 = hadd2(sqb);
                s0 += __shfl_xor_sync(FULLMASK, s0, 16);
                s1 += __shfl_xor_sync(FULLMASK, s1, 16);
                float s = b16 ? s1 : s0;
                s += __shfl_xor_sync(FULLMASK, s, 8);
                s += __shfl_xor_sync(FULLMASK, s, 4);
                s += __shfl_xor_sync(FULLMASK, s, 2);
                s += __shfl_xor_sync(FULLMASK, s, 1);
                if ((lane & 15) == 0)
                    sqsm[kh*TT + t + (b16 ? 1 : 0)] = s;
            }
        }
        __syncthreads();

        // ---- Phase C: sinkhorn + routing (cell-parallel, threads 0..255) ----
        if (tid < 256) {
            int t    = tid >> 4;        // token 0..15
            int cell = c_cell;          // i = cell>>2, j = cell&3
            int grp  = lane & 16;       // 16-lane group base within warp
            float rs = rsqrtf((sqsm[t] + sqsm[TT + t]) * (1.0f/1024.0f) + 1e-5f);
            const float* dp0 = dotsp + t*24;
            const float* dp1 = dotsp + (TT + t)*24;

            float z = a_res * ((dp0[8 + cell] + dp1[8 + cell]) * rs) + c_bres;
            float z1 = __shfl_xor_sync(FULLMASK, z, 1);
            float z2 = __shfl_xor_sync(FULLMASK, z, 2);
            float z3 = __shfl_xor_sync(FULLMASK, z, 3);
            float m1 = fmaxf(fmaxf(z, z1), fmaxf(z2, z3));
            float m4 = __shfl_xor_sync(FULLMASK, m1, 4);
            float m8 = __shfl_xor_sync(FULLMASK, m1, 8);
            float mc = __shfl_xor_sync(FULLMASK, m1, 12);
            float mx = fmaxf(fmaxf(m1, m4), fmaxf(m8, mc));
            float p = __expf(z - mx);

#pragma unroll
            for (int it = 0; it < 20; it++) {
                float c1 = __shfl_xor_sync(FULLMASK, p, 4);
                float c2 = __shfl_xor_sync(FULLMASK, p, 8);
                float c3 = __shfl_xor_sync(FULLMASK, p, 12);
                p = __fdividef(p, ((p + c1) + (c2 + c3)) + 1e-8f);
                float r1 = __shfl_xor_sync(FULLMASK, p, 1);
                float r2 = __shfl_xor_sync(FULLMASK, p, 2);
                float r3 = __shfl_xor_sync(FULLMASK, p, 3);
                p = __fdividef(p, ((p + r1) + (r2 + r3)) + 1e-8f);
            }

            float hv = 0.f;
            float dd = (dp0[cell] + dp1[cell]) * rs;   // valid for cell < 8
            if (cell < 4) {
                hv = __fdividef(1.0f, 1.0f + __expf(-(a_pre * dd + c_bph)));
            } else if (cell < 8) {
                hv = __fdividef(2.0f, 1.0f + __expf(-(a_post * dd + c_bph)));
            }
            int ii = cell >> 2, jj = cell & 3;
            float hpre_j  = __shfl_sync(FULLMASK, hv, grp + jj);
            float hpost_i = __shfl_sync(FULLMASK, hv, grp + 4 + ii);
            coef[t*16 + cell] = p + hpost_i * hpre_j;
        }
        __syncthreads();

        // ---- Phase D: mixing, 1024 (token,chunk) tasks over 384 threads ----
        {
            const float4* cf4 = reinterpret_cast<const float4*>(coef);
            for (int i = tid; i < 1024; i += NTHR) {
                int t  = i >> 6;
                int c4 = i & 63;
                float4 m0 = cf4[t*4 + 0];
                float4 m1 = cf4[t*4 + 1];
                float4 m2 = cf4[t*4 + 2];
                float4 m3 = cf4[t*4 + 3];
                const float4* x4 = reinterpret_cast<const float4*>(xb) + t*256;
                float4 xj0 = x4[0*64 + c4];
                float4 xj1 = x4[1*64 + c4];
                float4 xj2 = x4[2*64 + c4];
                float4 xj3 = x4[3*64 + c4];
                float4* o4 = reinterpret_cast<float4*>(out)
                           + ((size_t)tile*TT + t) * 256;
                float4 o;
                o.x = m0.x*xj0.x + m0.y*xj1.x + m0.z*xj2.x + m0.w*xj3.x;
                o.y = m0.x*xj0.y + m0.y*xj1.y + m0.z*xj2.y + m0.w*xj3.y;
                o.z = m0.x*xj0.z + m0.y*xj1.z + m0.z*xj2.z + m0.w*xj3.z;
                o.w = m0.x*xj0.w + m0.y*xj1.w + m0.z*xj2.w + m0.w*xj3.w;
                o4[0*64 + c4] = o;
                o.x = m1.x*xj0.x + m1.y*xj1.x + m1.z*xj2.x + m1.w*xj3.x;
                o.y = m1.x*xj0.y + m1.y*xj1.y + m1.z*xj2.y + m1.w*xj3.y;
                o.z = m1.x*xj0.z + m1.y*xj1.z + m1.z*xj2.z + m1.w*xj3.z;
                o.w = m1.x*xj0.w + m1.y*xj1.w + m1.z*xj2.w + m1.w*xj3.w;
                o4[1*64 + c4] = o;
                o.x = m2.x*xj0.x + m2.y*xj1.x + m2.z*xj2.x + m2.w*xj3.x;
                o.y = m2.x*xj0.y + m2.y*xj1.y + m2.z*xj2.y + m2.w*xj3.y;
                o.z = m2.x*xj0.z + m2.y*xj1.z + m2.z*xj2.z + m2.w*xj3.z;
                o.w = m2.x*xj0.w + m2.y*xj1.w + m2.z*xj2.w + m2.w*xj3.w;
                o4[2*64 + c4] = o;
                o.x = m3.x*xj0.x + m3.y*xj1.x + m3.z*xj2.x + m3.w*xj3.x;
                o.y = m3.x*xj0.y + m3.y*xj1.y + m3.z*xj2.y + m3.w*xj3.y;
                o.z = m3.x*xj0.z + m3.y*xj1.z + m3.z*xj2.z + m3.w*xj3.z;
                o.w = m3.x*xj0.w + m3.y*xj1.w + m3.z*xj2.w + m3.w*xj3.w;
                o4[3*64 + c4] = o;
            }
        }
        __syncthreads();   // xb free for reuse by the prefetch 2 tiles ahead
        buf ^= 1;
    }
}

extern "C" void kernel_launch(void* const* d_in, const int* in_sizes, int n_in,
                              void* d_out, int out_size) {
    const float* x      = (const float*)d_in[0];
    const float* scale  = (const float*)d_in[1];
    const float* w_pre  = (const float*)d_in[2];
    const float* w_post = (const float*)d_in[3];
    const float* w_res  = (const float*)d_in[4];
    const float* apre   = (const float*)d_in[5];
    const float* apost  = (const float*)d_in[6];
    const float* ares   = (const float*)d_in[7];
    const float* b_pre  = (const float*)d_in[8];
    const float* b_post = (const float*)d_in[9];
    const float* b_res  = (const float*)d_in[10];
    float* out = (float*)d_out;

    int BT = in_sizes[0] / NC;        // 32768 tokens
    int nTiles = BT / TT;             // 2048

    size_t smemBytes = (size_t)SMEM_FLOATS * sizeof(float);   // ~135 KB

    int dev = 0;
    cudaGetDevice(&dev);
    int sms = 148;
    cudaDeviceGetAttribute(&sms, cudaDevAttrMultiProcessorCount, dev);
    cudaFuncSetAttribute(fused_streams_kernel,
                         cudaFuncAttributeMaxDynamicSharedMemorySize,
                         (int)smemBytes);

    int grid = sms < nTiles ? sms : nTiles;

    fused_streams_kernel<<<grid, NTHR, smemBytes>>>(
        x, scale, w_pre, w_post, w_res,
        apre, apost, ares, b_pre, b_post, b_res,
        out, nTiles);
}